// round 17
// baseline (speedup 1.0000x reference)
#include <cuda_runtime.h>
#include <cuda_fp16.h>
#include <cstdint>

// Shapes (fixed)
#define NB 4
#define NN 512
#define ND 2
#define NH 64
#define NO 2

// Scratch
__device__ float g_s[NB * NN * NH];

// ---------------------------------------------------------------------------
__device__ __forceinline__ uint32_t smem_u32(const void* p) {
    uint32_t a;
    asm("{ .reg .u64 t; cvta.to.shared.u64 t, %1; cvt.u32.u64 %0, t; }" : "=r"(a) : "l"(p));
    return a;
}
__device__ __forceinline__ uint32_t pack_f16x2(float a, float b) {
    uint32_t r;
    asm("cvt.rn.f16x2.f32 %0, %2, %1;" : "=r"(r) : "f"(a), "f"(b));
    return r;
}
__device__ __forceinline__ uint32_t h2u(__half2 v) {
    return *reinterpret_cast<uint32_t*>(&v);
}
__device__ __forceinline__ __half2 u2h(uint32_t v) {
    return *reinterpret_cast<__half2*>(&v);
}
__device__ __forceinline__ void ldsm_x2(uint32_t& b0, uint32_t& b1, uint32_t addr) {
    asm volatile("ldmatrix.sync.aligned.m8n8.x2.shared.b16 {%0,%1}, [%2];"
                 : "=r"(b0), "=r"(b1) : "r"(addr));
}
__device__ __forceinline__ void mma16816(float& c0, float& c1, float& c2, float& c3,
                                         uint32_t a0, uint32_t a1, uint32_t a2, uint32_t a3,
                                         uint32_t b0, uint32_t b1) {
    asm volatile("mma.sync.aligned.m16n8k16.row.col.f32.f16.f16.f32 "
                 "{%0,%1,%2,%3}, {%4,%5,%6,%7}, {%8,%9}, {%0,%1,%2,%3};"
                 : "+f"(c0), "+f"(c1), "+f"(c2), "+f"(c3)
                 : "r"(a0), "r"(a1), "r"(a2), "r"(a3), "r"(b0), "r"(b1));
}

#define WSTR 72
#define NODES 4

// ---------------------------------------------------------------------------
// Edge kernel: one CTA per 4 nodes, 256 thr, (256,2).
// A fragments in registers; bias folded into MMA accumulator init; x staged
// as pre-converted broadcast half2 pairs (zero cvt in mainloop).
// ---------------------------------------------------------------------------
__global__ void __launch_bounds__(256, 2) k_edge_mma(const float* __restrict__ x,
                                                     const float* __restrict__ adj,
                                                     const float* __restrict__ Wn2e,
                                                     const float* __restrict__ bn2e,
                                                     const float* __restrict__ We2e,
                                                     const float* __restrict__ be2e) {
    __shared__ __align__(16) char wpool[64 * WSTR * 2];   // Wsh, then xh
    __shared__ float su[NODES][64];
    __shared__ float red[8][32];

    __half* Wsh = (__half*)wpool;
    uint2* xh = (uint2*)wpool;        // [512]: {h2(x0,x0), h2(x1,x1)}

    int t = threadIdx.x;
    int w = t >> 5;
    int lane = t & 31;
    int bi = blockIdx.x;              // 0..511
    int b = bi >> 7;
    int i0 = (bi & 127) * NODES;
    int mq = w & 3;
    int nq = w >> 2;

    uint32_t Wb = smem_u32(wpool);

    // ---- stage W_e2e [64h][64k] as fp16 ----
    {
        int h = t >> 2;
        int kb = (t & 3) * 16;
        const float* wrow = We2e + h * 64 + kb;
        #pragma unroll
        for (int c = 0; c < 2; ++c) {
            float4 f0 = *(const float4*)(wrow + c * 8);
            float4 f1 = *(const float4*)(wrow + c * 8 + 4);
            uint4 pk;
            pk.x = pack_f16x2(f0.x, f0.y);
            pk.y = pack_f16x2(f0.z, f0.w);
            pk.z = pack_f16x2(f1.x, f1.y);
            pk.w = pack_f16x2(f1.z, f1.w);
            *(uint4*)(Wsh + h * WSTR + kb + c * 8) = pk;
        }
    }
    // u for all 4 nodes (256 threads: ii = t>>6, h = t&63)
    {
        int ii = t >> 6;
        int h = t & 63;
        float4 wr = *(const float4*)(Wn2e + h * 4);
        float xi0 = x[(b * NN + i0 + ii) * 2 + 0];
        float xi1 = x[(b * NN + i0 + ii) * 2 + 1];
        su[ii][h] = bn2e[h] + wr.x * xi0 + wr.y * xi1;
    }
    __syncthreads();

    // ---- hoist B fragments ----
    uint32_t Bfr[4][4][2];
    #pragma unroll
    for (int k = 0; k < 4; ++k) {
        #pragma unroll
        for (int nt = 0; nt < 4; ++nt) {
            uint32_t addr = Wb + (uint32_t)(((nq * 32 + nt * 8 + (lane & 7)) * WSTR
                                             + k * 16 + ((lane >> 3) & 1) * 8) * 2);
            ldsm_x2(Bfr[k][nt][0], Bfr[k][nt][1], addr);
        }
    }
    __syncthreads();   // Wsh dead

    // ---- stage x as pre-converted broadcast half2 pairs ----
    {
        const float2* xb = (const float2*)(x + b * NN * 2);
        for (int j = t; j < NN; j += 256) {
            float2 xv = xb[j];
            uint2 pk;
            pk.x = h2u(__float2half2_rn(xv.x));
            pk.y = h2u(__float2half2_rn(xv.y));
            xh[j] = pk;
        }
    }

    // ---- per-thread k constants ----
    int klo = (lane & 3) * 2;
    __half2 w2p[4][2], w3p[4][2];
    #pragma unroll
    for (int kc = 0; kc < 4; ++kc) {
        #pragma unroll
        for (int kh = 0; kh < 2; ++kh) {
            int k0 = kc * 16 + kh * 8 + klo;
            float4 wr0 = *(const float4*)(Wn2e + k0 * 4);
            float4 wr1 = *(const float4*)(Wn2e + (k0 + 1) * 4);
            w2p[kc][kh] = __floats2half2_rn(wr0.z, wr1.z);
            w3p[kc][kh] = __floats2half2_rn(wr0.w, wr1.w);
        }
    }
    float sb2r[4][2];
    #pragma unroll
    for (int nt = 0; nt < 4; ++nt) {
        sb2r[nt][0] = be2e[nq * 32 + nt * 8 + klo];
        sb2r[nt][1] = be2e[nq * 32 + nt * 8 + klo + 1];
    }
    __syncthreads();   // xh staged, su visible

    const __half2 z2 = __float2half2_rn(0.f);
    int r0 = lane >> 2;
    int rbase = mq * 32 + r0;

    for (int ii = 0; ii < NODES; ++ii) {
        int i = i0 + ii;

        __half2 up[4][2];
        #pragma unroll
        for (int kc = 0; kc < 4; ++kc) {
            #pragma unroll
            for (int kh = 0; kh < 2; ++kh) {
                int k0 = kc * 16 + kh * 8 + klo;
                up[kc][kh] = __floats2half2_rn(su[ii][k0], su[ii][k0 + 1]);
            }
        }

        const float* adjrow = adj + i * NN;
        float adjr[4][2][2];
        #pragma unroll
        for (int jt = 0; jt < 4; ++jt) {
            #pragma unroll
            for (int s = 0; s < 2; ++s) {
                adjr[jt][s][0] = adjrow[jt * 128 + rbase + s * 16];
                adjr[jt][s][1] = adjrow[jt * 128 + rbase + s * 16 + 8];
            }
        }

        float sacc[8];
        #pragma unroll
        for (int q = 0; q < 8; ++q) sacc[q] = 0.f;

        #pragma unroll
        for (int jt = 0; jt < 4; ++jt) {
            int jbase = jt << 7;

            #pragma unroll
            for (int s = 0; s < 2; ++s) {
                int j0 = jbase + mq * 32 + s * 16 + r0;
                uint2 xra = xh[j0];
                uint2 xrb = xh[j0 + 8];
                __half2 xa0 = u2h(xra.x), xa1 = u2h(xra.y);
                __half2 xb0 = u2h(xrb.x), xb1 = u2h(xrb.y);

                // acc init = bias (folded add)
                float acc[4][4];
                #pragma unroll
                for (int nt = 0; nt < 4; ++nt) {
                    acc[nt][0] = sb2r[nt][0]; acc[nt][1] = sb2r[nt][1];
                    acc[nt][2] = sb2r[nt][0]; acc[nt][3] = sb2r[nt][1];
                }

                #pragma unroll
                for (int kc = 0; kc < 4; ++kc) {
                    __half2 a0 = __hmax2(__hfma2(w3p[kc][0], xa1,
                                    __hfma2(w2p[kc][0], xa0, up[kc][0])), z2);
                    __half2 a1 = __hmax2(__hfma2(w3p[kc][0], xb1,
                                    __hfma2(w2p[kc][0], xb0, up[kc][0])), z2);
                    __half2 a2 = __hmax2(__hfma2(w3p[kc][1], xa1,
                                    __hfma2(w2p[kc][1], xa0, up[kc][1])), z2);
                    __half2 a3 = __hmax2(__hfma2(w3p[kc][1], xb1,
                                    __hfma2(w2p[kc][1], xb0, up[kc][1])), z2);
                    uint32_t ua0 = h2u(a0), ua1 = h2u(a1), ua2 = h2u(a2), ua3 = h2u(a3);
                    #pragma unroll
                    for (int nt = 0; nt < 4; ++nt)
                        mma16816(acc[nt][0], acc[nt][1], acc[nt][2], acc[nt][3],
                                 ua0, ua1, ua2, ua3, Bfr[kc][nt][0], Bfr[kc][nt][1]);
                }

                float aj0 = adjr[jt][s][0];
                float aj1 = adjr[jt][s][1];
                #pragma unroll
                for (int nt = 0; nt < 4; ++nt) {
                    sacc[nt * 2 + 0] += aj0 * fmaxf(acc[nt][0], 0.f)
                                      + aj1 * fmaxf(acc[nt][2], 0.f);
                    sacc[nt * 2 + 1] += aj0 * fmaxf(acc[nt][1], 0.f)
                                      + aj1 * fmaxf(acc[nt][3], 0.f);
                }
            }
        }

        // ---- reduce and store s ----
        #pragma unroll
        for (int q = 0; q < 8; ++q) {
            sacc[q] += __shfl_down_sync(0xFFFFFFFFu, sacc[q], 16);
            sacc[q] += __shfl_down_sync(0xFFFFFFFFu, sacc[q], 8);
            sacc[q] += __shfl_down_sync(0xFFFFFFFFu, sacc[q], 4);
        }
        if (lane < 4) {
            #pragma unroll
            for (int nt = 0; nt < 4; ++nt) {
                red[w][nt * 8 + lane * 2 + 0] = sacc[nt * 2 + 0];
                red[w][nt * 8 + lane * 2 + 1] = sacc[nt * 2 + 1];
            }
        }
        __syncthreads();
        if (t < 64) {
            int nq2 = t >> 5;
            int hh = t & 31;
            g_s[(b * NN + i) * 64 + t] = red[nq2 * 4 + 0][hh] + red[nq2 * 4 + 1][hh]
                                       + red[nq2 * 4 + 2][hh] + red[nq2 * 4 + 3][hh];
        }
        __syncthreads();
    }
}

// ---------------------------------------------------------------------------
// Head kernel (R11-measured, 15.0 us)
// ---------------------------------------------------------------------------
__global__ void __launch_bounds__(256) k_head(const float* __restrict__ x,
                                              const float* __restrict__ We2n,
                                              const float* __restrict__ be2n,
                                              const float* __restrict__ Wn2n,
                                              const float* __restrict__ bn2n,
                                              const float* __restrict__ Wo1,
                                              const float* __restrict__ bo1,
                                              const float* __restrict__ Wo2,
                                              const float* __restrict__ bo2,
                                              float* __restrict__ out) {
    __shared__ float2 wA[66 * 33];
    __shared__ float2 wB[64 * 33];
    __shared__ float sio[8][64];
    __shared__ float sb[3][64];
    __shared__ float swo2[128];
    __shared__ float sb2o[2];
    __shared__ float sxn[8][2];

    int t = threadIdx.x;
    int w = t >> 5;
    int lane = t & 31;
    int nbase = blockIdx.x * 8;

    for (int idx = t; idx < 2048; idx += 256) {
        int k = idx & 63, h = idx >> 6;
        wA[k * 33 + h] = make_float2(We2n[h * 64 + k], We2n[(h + 32) * 64 + k]);
    }
    {
        int idx = t;
        sio[idx >> 6][idx & 63] = g_s[(nbase + (idx >> 6)) * 64 + (idx & 63)];
        idx = t + 256;
        sio[idx >> 6][idx & 63] = g_s[(nbase + (idx >> 6)) * 64 + (idx & 63)];
    }
    if (t < 64) { sb[0][t] = be2n[t]; sb[1][t] = bn2n[t]; sb[2][t] = bo1[t]; }
    if (t < 128) swo2[t] = Wo2[t];
    if (t < 2) sb2o[t] = bo2[t];
    if (t < 16) sxn[t >> 1][t & 1] = x[(nbase + (t >> 1)) * 2 + (t & 1)];
    __syncthreads();

    float2 pf[8];
    #pragma unroll
    for (int c = 0; c < 8; ++c) {
        int idx = t + c * 256;
        int k = idx & 63, h = idx >> 6;
        pf[c] = make_float2(Wn2n[h * 64 + k], Wn2n[(h + 32) * 64 + k]);
    }
    float a0 = sb[0][lane], a1 = sb[0][32 + lane];
    #pragma unroll 16
    for (int k = 0; k < 64; ++k) {
        float2 wv = wA[k * 33 + lane];
        float xv = sio[w][k];
        a0 = fmaf(wv.x, xv, a0);
        a1 = fmaf(wv.y, xv, a1);
    }
    a0 = fmaxf(a0, 0.f); a1 = fmaxf(a1, 0.f);
    __syncwarp();
    sio[w][lane] = a0; sio[w][32 + lane] = a1;
    #pragma unroll
    for (int c = 0; c < 8; ++c) {
        int idx = t + c * 256;
        int k = idx & 63, h = idx >> 6;
        wB[k * 33 + h] = pf[c];
    }
    __syncthreads();

    float2 pfo[9];
    #pragma unroll
    for (int c = 0; c < 9; ++c) {
        int idx = t + c * 256;
        if (idx < 2112) {
            int cc = idx / 32, h = idx & 31;
            pfo[c] = make_float2(Wo1[h * 66 + cc], Wo1[(h + 32) * 66 + cc]);
        }
    }
    a0 = sb[1][lane]; a1 = sb[1][32 + lane];
    #pragma unroll 16
    for (int k = 0; k < 64; ++k) {
        float2 wv = wB[k * 33 + lane];
        float xv = sio[w][k];
        a0 = fmaf(wv.x, xv, a0);
        a1 = fmaf(wv.y, xv, a1);
    }
    a0 = fmaxf(a0, 0.f); a1 = fmaxf(a1, 0.f);
    __syncwarp();
    sio[w][lane] = a0; sio[w][32 + lane] = a1;
    #pragma unroll
    for (int c = 0; c < 9; ++c) {
        int idx = t + c * 256;
        if (idx < 2112) {
            int cc = idx / 32, h = idx & 31;
            wA[cc * 33 + h] = pfo[c];
        }
    }
    __syncthreads();

    a0 = sb[2][lane]; a1 = sb[2][32 + lane];
    {
        float x0 = sxn[w][0], x1 = sxn[w][1];
        float2 wv0 = wA[0 * 33 + lane];
        float2 wv1 = wA[1 * 33 + lane];
        a0 = fmaf(wv0.x, x0, fmaf(wv1.x, x1, a0));
        a1 = fmaf(wv0.y, x0, fmaf(wv1.y, x1, a1));
    }
    #pragma unroll 16
    for (int k = 0; k < 64; ++k) {
        float2 wv = wA[(k + 2) * 33 + lane];
        float xv = sio[w][k];
        a0 = fmaf(wv.x, xv, a0);
        a1 = fmaf(wv.y, xv, a1);
    }
    a0 = fmaxf(a0, 0.f); a1 = fmaxf(a1, 0.f);

    #pragma unroll
    for (int o = 0; o < 2; ++o) {
        float p = swo2[o * 64 + lane] * a0 + swo2[o * 64 + 32 + lane] * a1;
        p += __shfl_down_sync(0xFFFFFFFFu, p, 16);
        p += __shfl_down_sync(0xFFFFFFFFu, p, 8);
        p += __shfl_down_sync(0xFFFFFFFFu, p, 4);
        p += __shfl_down_sync(0xFFFFFFFFu, p, 2);
        p += __shfl_down_sync(0xFFFFFFFFu, p, 1);
        if (lane == 0) out[(nbase + w) * 2 + o] = sb2o[o] + p;
    }
}

// ---------------------------------------------------------------------------
extern "C" void kernel_launch(void* const* d_in, const int* in_sizes, int n_in,
                              void* d_out, int out_size) {
    const float* input = (const float*)d_in[0];
    const float* adj   = (const float*)d_in[1];
    const float* W_n2e = (const float*)d_in[2];
    const float* b_n2e = (const float*)d_in[3];
    const float* W_e2e = (const float*)d_in[4];
    const float* b_e2e = (const float*)d_in[5];
    const float* W_e2n = (const float*)d_in[6];
    const float* b_e2n = (const float*)d_in[7];
    const float* W_n2n = (const float*)d_in[8];
    const float* b_n2n = (const float*)d_in[9];
    const float* W_o1  = (const float*)d_in[10];
    const float* b_o1  = (const float*)d_in[11];
    const float* W_o2  = (const float*)d_in[12];
    const float* b_o2  = (const float*)d_in[13];
    float* out = (float*)d_out;

    k_edge_mma<<<NB * NN / NODES, 256>>>(input, adj, W_n2e, b_n2e, W_e2e, b_e2e);
    k_head<<<NB * NN / 8, 256>>>(input, W_e2n, b_e2n, W_n2n, b_n2n,
                                 W_o1, b_o1, W_o2, b_o2, out);
}